// round 4
// baseline (speedup 1.0000x reference)
#include <cuda_runtime.h>

#define NB 64
#define NT 1024
#define MAXLAG 256
#define NPOS 2
#define NPAIR (NT/2)   /* 512 float4 = 1024 float2 */

// Scratch (device globals: no allocation allowed). Every slot fully written
// each launch -> no zero-init kernel needed, fully deterministic.
__device__ float g_msd_part[NPOS][NB][MAXLAG];
__device__ float g_per_traj[NB];

// ---------------------------------------------------------------------------
// lengths dtype is declared int64 in the reference, but JAX without x64
// silently produces int32. Decode robustly: view as int32 words; for a
// little-endian int64 buffer every odd word is a high word == 0 (values
// are < 2^31), while for an int32 buffer word 1 >= 512 != 0.
// All accesses in bounds for either layout.
// ---------------------------------------------------------------------------
__device__ __forceinline__ int read_len(const int* __restrict__ p, int b)
{
    return (p[1] == 0) ? p[2 * b] : p[b];
}

// ---------------------------------------------------------------------------
// Kernel 1: partial MSD sums.
// grid = (NB, NPOS), block = 256 threads (thread t <-> lag L = t+1).
// Each block loads its trajectory (8KB) into smem, then each thread walks
// positions p = chunk, chunk+NPOS, ... while p < len - L.
// Per warp-iter: y[p] broadcast (1 wf) + 32 consecutive float2 (2 wf).
// ---------------------------------------------------------------------------
__global__ __launch_bounds__(256) void msd_kernel(
    const float* __restrict__ traj,
    const int* __restrict__ lengths_raw)
{
    __shared__ float2 y[NT];

    const int b     = blockIdx.x;
    const int chunk = blockIdx.y;

    // Cooperative 16B-vector load of the trajectory row into smem.
    const float4* src = reinterpret_cast<const float4*>(traj + (size_t)b * NT * 2);
    float4* dst = reinterpret_cast<float4*>(y);
    #pragma unroll
    for (int i = threadIdx.x; i < NPAIR; i += 256)
        dst[i] = src[i];
    __syncthreads();

    const int L     = threadIdx.x + 1;
    const int len   = read_len(lengths_raw, b);
    const int bound = len - L;          // valid positions: p in [0, bound)

    float acc = 0.0f;
    #pragma unroll 4
    for (int p = chunk; p < bound; p += NPOS) {
        float2 s = y[p];
        float2 e = y[p + L];
        float dx = e.x - s.x;
        float dy = e.y - s.y;
        acc += dx * dx + dy * dy;
    }

    g_msd_part[chunk][b][threadIdx.x] = acc;
}

// ---------------------------------------------------------------------------
// Block-wide sum over 256 threads (8 warps).
// ---------------------------------------------------------------------------
__device__ __forceinline__ float block_sum_256(float v, float* sbuf)
{
    #pragma unroll
    for (int o = 16; o > 0; o >>= 1)
        v += __shfl_down_sync(0xffffffffu, v, o);
    const int warp = threadIdx.x >> 5;
    if ((threadIdx.x & 31) == 0) sbuf[warp] = v;
    __syncthreads();
    if (threadIdx.x < 8) {
        v = sbuf[threadIdx.x];
        #pragma unroll
        for (int o = 4; o > 0; o >>= 1)
            v += __shfl_down_sync(0xffu, v, o);
        if (threadIdx.x == 0) sbuf[0] = v;
    }
    __syncthreads();
    float r = sbuf[0];
    __syncthreads();   // sbuf reused by caller
    return r;
}

// ---------------------------------------------------------------------------
// Kernel 2: per-trajectory loss.
// grid = NB, block = 256 (thread t <-> lag L = t+1).
// ---------------------------------------------------------------------------
__global__ __launch_bounds__(256) void finalize_kernel(
    const float* __restrict__ alpha_pred,
    const int* __restrict__ lengths_raw)
{
    __shared__ float sbuf[8];

    const int b   = blockIdx.x;
    const int t   = threadIdx.x;
    const int L   = t + 1;
    const int len = read_len(lengths_raw, b);

    float msd = 0.0f;
    #pragma unroll
    for (int c = 0; c < NPOS; c++)
        msd += g_msd_part[c][b][t];

    const float count = fmaxf((float)(len - L), 1.0f);
    msd /= count;

    const float log_msd = logf(msd + 1e-8f);
    const float log_lag = logf((float)L);
    const float alpha   = alpha_pred[b];
    const float mask    = (len > L) ? 1.0f : 0.0f;   // always 1 for these shapes
    const float resid   = log_msd - alpha * log_lag;

    const float denom     = fmaxf(block_sum_256(mask, sbuf), 1.0f);
    const float intercept = block_sum_256(resid * mask, sbuf) / denom;

    const float err = alpha * log_lag + intercept - log_msd;
    const float per_traj = block_sum_256(err * err * mask, sbuf) / denom;

    if (t == 0) g_per_traj[b] = per_traj;
}

// ---------------------------------------------------------------------------
// Kernel 3: mean over 64 trajectories -> scalar output.
// ---------------------------------------------------------------------------
__global__ void mean_kernel(float* __restrict__ out)
{
    __shared__ float s[2];
    float v = g_per_traj[threadIdx.x];
    #pragma unroll
    for (int o = 16; o > 0; o >>= 1)
        v += __shfl_down_sync(0xffffffffu, v, o);
    if ((threadIdx.x & 31) == 0) s[threadIdx.x >> 5] = v;
    __syncthreads();
    if (threadIdx.x == 0) out[0] = (s[0] + s[1]) * (1.0f / (float)NB);
}

// ---------------------------------------------------------------------------
extern "C" void kernel_launch(void* const* d_in, const int* in_sizes, int n_in,
                              void* d_out, int out_size)
{
    const float* alpha       = (const float*)d_in[0];   // [64]
    const float* traj        = (const float*)d_in[1];   // [64,1024,2]
    const int*   lengths_raw = (const int*)d_in[2];     // [64] int32 or int64
    float* out = (float*)d_out;

    dim3 g1(NB, NPOS);
    msd_kernel<<<g1, 256>>>(traj, lengths_raw);
    finalize_kernel<<<NB, 256>>>(alpha, lengths_raw);
    mean_kernel<<<1, 64>>>(out);
}

// round 5
// speedup vs baseline: 1.2759x; 1.2759x over previous
#include <cuda_runtime.h>

#define NB     64
#define NT     1024
#define MAXLAG 256
#define NPOS   16          /* position-interleave chunks -> NB*NPOS = 1024 blocks */
#define NPAIR  (NT/2)      /* 512 float4 per trajectory */

// Scratch (device globals; allocation is forbidden). Partial sums are fully
// overwritten every launch. Counters self-reset (last consumer writes 0) so
// every graph replay starts from the same state -> deterministic.
__device__ float    g_msd_part[NB][NPOS][MAXLAG];
__device__ float    g_per_traj[NB];
__device__ unsigned g_cnt_traj[NB];      // zero-init, reset by finalizer
__device__ unsigned g_cnt_final;         // zero-init, reset by mean block

// ---------------------------------------------------------------------------
// lengths is declared int64 in the reference but JAX w/o x64 emits int32.
// View as int32 words: little-endian int64 has every odd word == 0 (values
// < 2^31); an int32 buffer has word1 >= 512. Discriminate on p[1]==0.
// ---------------------------------------------------------------------------
__device__ __forceinline__ int read_len(const int* __restrict__ p, int b)
{
    return (p[1] == 0) ? p[2 * b] : p[b];
}

__device__ __forceinline__ float block_sum_256(float v, float* sbuf)
{
    #pragma unroll
    for (int o = 16; o > 0; o >>= 1)
        v += __shfl_down_sync(0xffffffffu, v, o);
    const int warp = threadIdx.x >> 5;
    if ((threadIdx.x & 31) == 0) sbuf[warp] = v;
    __syncthreads();
    if (threadIdx.x < 8) {
        v = sbuf[threadIdx.x];
        #pragma unroll
        for (int o = 4; o > 0; o >>= 1)
            v += __shfl_down_sync(0xffu, v, o);
        if (threadIdx.x == 0) sbuf[0] = v;
    }
    __syncthreads();
    float r = sbuf[0];
    __syncthreads();   // sbuf reused by caller
    return r;
}

// ---------------------------------------------------------------------------
// Single fused kernel.
// grid = (NB, NPOS), block = 256 (thread t <-> lag L = t+1).
// Phase 1 (all blocks): partial MSD sums over interleaved positions.
// Phase 2 (last block per b): per-trajectory log-fit loss.
// Phase 3 (last finalizer): mean over 64 trajectories -> out[0].
// ---------------------------------------------------------------------------
__global__ __launch_bounds__(256) void fused_kernel(
    const float* __restrict__ traj,
    const int*   __restrict__ lengths_raw,
    const float* __restrict__ alpha_pred,
    float*       __restrict__ out)
{
    __shared__ float2   y[NT];
    __shared__ float    sbuf[8];
    __shared__ unsigned s_flag;

    const int b     = blockIdx.x;
    const int chunk = blockIdx.y;
    const int t     = threadIdx.x;
    const int L     = t + 1;

    // ---- Phase 1: MSD partial sums -------------------------------------
    {
        const float4* src = reinterpret_cast<const float4*>(traj + (size_t)b * NT * 2);
        float4* dst = reinterpret_cast<float4*>(y);
        #pragma unroll
        for (int i = t; i < NPAIR; i += 256)
            dst[i] = src[i];
    }
    __syncthreads();

    const int len   = read_len(lengths_raw, b);
    const int bound = len - L;               // valid positions: [0, bound)

    // Packed fp32x2 accumulation: d = e - s via fma(s, -1, e); acc += d*d.
    const unsigned long long NEG1 = 0xBF800000BF800000ULL;   // {-1.f, -1.f}
    unsigned long long acc = 0ULL;                            // {0.f, 0.f}

    const unsigned long long* y64 = reinterpret_cast<const unsigned long long*>(y);
    #pragma unroll 4
    for (int p = chunk; p < bound; p += NPOS) {
        unsigned long long s = y64[p];
        unsigned long long e = y64[p + L];
        unsigned long long d;
        asm("fma.rn.f32x2 %0, %1, %2, %3;" : "=l"(d)   : "l"(s), "l"(NEG1), "l"(e));
        asm("fma.rn.f32x2 %0, %1, %1, %2;" : "=l"(acc) : "l"(d), "l"(acc));
    }
    float ax, ay;
    asm("mov.b64 {%0, %1}, %2;" : "=f"(ax), "=f"(ay) : "l"(acc));

    g_msd_part[b][chunk][t] = ax + ay;

    // ---- Elect finalizer block for trajectory b ------------------------
    __threadfence();
    __syncthreads();
    if (t == 0) s_flag = atomicAdd(&g_cnt_traj[b], 1u);
    __syncthreads();
    if (s_flag != NPOS - 1) return;          // uniform per block

    // ---- Phase 2: per-trajectory loss (one block per b) ----------------
    if (t == 0) g_cnt_traj[b] = 0u;          // reset for next launch

    float msd = 0.0f;
    #pragma unroll
    for (int c = 0; c < NPOS; c++)
        msd += g_msd_part[b][c][t];

    const float count = fmaxf((float)(len - L), 1.0f);
    msd /= count;

    const float log_msd = logf(msd + 1e-8f);
    const float log_lag = logf((float)L);
    const float alpha   = alpha_pred[b];
    const float mask    = (len > L) ? 1.0f : 0.0f;
    const float resid   = log_msd - alpha * log_lag;

    const float denom     = fmaxf(block_sum_256(mask, sbuf), 1.0f);
    const float intercept = block_sum_256(resid * mask, sbuf) / denom;

    const float err = alpha * log_lag + intercept - log_msd;
    const float per_traj = block_sum_256(err * err * mask, sbuf) / denom;

    // ---- Elect mean block ---------------------------------------------
    if (t == 0) {
        g_per_traj[b] = per_traj;
        __threadfence();
        s_flag = atomicAdd(&g_cnt_final, 1u);
    }
    __syncthreads();
    if (s_flag != NB - 1) return;

    // ---- Phase 3: mean over trajectories -------------------------------
    if (t == 0) g_cnt_final = 0u;            // reset for next launch

    float v = (t < NB) ? g_per_traj[t] : 0.0f;
    if (t < 64) {
        #pragma unroll
        for (int o = 16; o > 0; o >>= 1)
            v += __shfl_down_sync(0xffffffffu, v, o);
        if ((t & 31) == 0) sbuf[t >> 5] = v;
    }
    __syncthreads();
    if (t == 0) out[0] = (sbuf[0] + sbuf[1]) * (1.0f / (float)NB);
}

// ---------------------------------------------------------------------------
extern "C" void kernel_launch(void* const* d_in, const int* in_sizes, int n_in,
                              void* d_out, int out_size)
{
    const float* alpha       = (const float*)d_in[0];   // [64]
    const float* traj        = (const float*)d_in[1];   // [64,1024,2]
    const int*   lengths_raw = (const int*)d_in[2];     // [64] int32 or int64
    float* out = (float*)d_out;

    dim3 grid(NB, NPOS);
    fused_kernel<<<grid, 256>>>(traj, lengths_raw, alpha, out);
}